// round 15
// baseline (speedup 1.0000x reference)
#include <cuda_runtime.h>
#include <cuda_fp16.h>
#include <cstdint>

#define NMAX 100000
#define EMAX 1600000
#define SLOT 128
#define EPSV 1e-16f

// ---------------- scratch (static device globals; no allocation) ----------------
__device__ __half g_xl1h[NMAX * 64];   // layer1 features, fp16 (gather table)
__device__ float  g_asrc1[NMAX * 8];
__device__ float  g_adst1[NMAX * 8];
__device__ __half g_x2h[NMAX * 16];    // layer2 features, fp16 (gather table)
__device__ float  g_asrc2[NMAX];
__device__ float  g_adst2[NMAX];
__device__ int g_cnt[NMAX];
__device__ int g_csrc[NMAX * SLOT];
// W1 in mma fragment layout: [ktile(64)][ntile(8)][lane(32)][reg(2)], hi & lo tf32
__device__ uint32_t g_w1hi[512 * 64];
__device__ uint32_t g_w1lo[512 * 64];

__device__ __forceinline__ float lrelu(float x) { return x > 0.0f ? x : 0.2f * x; }

__device__ __forceinline__ uint32_t f2tf32(float f) {
    uint32_t r;
    asm("cvt.rna.tf32.f32 %0, %1;" : "=r"(r) : "f"(f));
    return r;
}

#define MMA_TF32(c, a, b) \
    asm volatile("mma.sync.aligned.m16n8k8.row.col.f32.tf32.tf32.f32 " \
                 "{%0,%1,%2,%3}, {%4,%5,%6,%7}, {%8,%9}, {%0,%1,%2,%3};" \
                 : "+f"((c)[0]), "+f"((c)[1]), "+f"((c)[2]), "+f"((c)[3]) \
                 : "r"((a)[0]), "r"((a)[1]), "r"((a)[2]), "r"((a)[3]), \
                   "r"((b).x), "r"((b).y))

// ================= zero counters + W1 hi/lo fragment precompute =================
__global__ void zero_prep_kernel(const float* __restrict__ W, int n) {
    int i = blockIdx.x * blockDim.x + threadIdx.x;
    if (i < n) g_cnt[i] = 0;
    if (i < 512 * 64) {
        int k = i >> 6, nn = i & 63;
        float wv = W[i];
        uint32_t hi = f2tf32(wv);
        uint32_t lo = f2tf32(wv - __uint_as_float(hi));
        int pos = ((((k >> 3) * 8 + (nn >> 3)) * 32 + ((nn & 7) * 4 + (k & 3))) << 1) + ((k >> 2) & 1);
        g_w1hi[pos] = hi;
        g_w1lo[pos] = lo;
    }
}

// ================= fused mma.sync 3xTF32 GEMM1 (+attn coeffs) and edge scatter =================
// Register double-buffered A staging: chunk c+1's gmem loads issue before chunk c's MMAs.
__global__ void __launch_bounds__(256) gemm1_mma_scatter_kernel(
        const float* __restrict__ X,
        const float* __restrict__ att_src, const float* __restrict__ att_dst,
        const int* __restrict__ src, const int* __restrict__ dst,
        int M, int E, int gemmBlocks, int scatterBlocks) {
    if (blockIdx.x >= (unsigned)gemmBlocks) {
        int sb = blockIdx.x - gemmBlocks;
        int stride = scatterBlocks * 256;
        for (int i = sb * 256 + threadIdx.x; i < E; i += stride) {
            int d = dst[i];
            int pos = atomicAdd(&g_cnt[d], 1);
            if (pos < SLOT) g_csrc[(size_t)d * SLOT + pos] = src[i];
        }
        return;
    }
    __shared__ __align__(16) uint32_t sAhi[4096];
    __shared__ __align__(16) uint32_t sAlo[4096];
    __shared__ float s_as[64], s_ad[64];

    int tid = threadIdx.x;
    int w = tid >> 5, lane = tid & 31;
    int g = lane >> 2, t = lane & 3;
    int m0 = blockIdx.x * 256;

    if (tid < 64) { s_as[tid] = att_src[tid]; s_ad[tid] = att_dst[tid]; }

    // loader geometry (fixed per thread): row = tid>>2? No: idx4 = tid + j*256
    int arow = tid >> 2, acol4 = tid & 3;   // used with j offsets below
    int grow = m0 + arow;                    // rows covered: arow + j*64
    float C[2][8][4];
#pragma unroll
    for (int m = 0; m < 2; m++)
#pragma unroll
        for (int nt = 0; nt < 8; nt++)
#pragma unroll
            for (int r = 0; r < 4; r++) C[m][nt][r] = 0.0f;

    float4 v[4];
    // prefetch chunk 0
#pragma unroll
    for (int j = 0; j < 4; j++) {
        int row = arow + j * 64;
        int gr = m0 + row;
        v[j] = (gr < M) ? *(const float4*)(X + (size_t)gr * 512 + acol4 * 4)
                        : make_float4(0.f, 0.f, 0.f, 0.f);
    }

    for (int c = 0; c < 32; c++) {
        __syncthreads();   // previous chunk's MMAs done; smem free
        // ---- convert+store prefetched regs to frag-layout smem ----
#pragma unroll
        for (int j = 0; j < 4; j++) {
            int row = arow + j * 64;
            uint32_t h0 = f2tf32(v[j].x), h1 = f2tf32(v[j].y), h2 = f2tf32(v[j].z), h3 = f2tf32(v[j].w);
            uint32_t l0 = f2tf32(v[j].x - __uint_as_float(h0));
            uint32_t l1 = f2tf32(v[j].y - __uint_as_float(h1));
            uint32_t l2 = f2tf32(v[j].z - __uint_as_float(h2));
            uint32_t l3 = f2tf32(v[j].w - __uint_as_float(h3));
            int kt = acol4 >> 1, chigh = acol4 & 1;
            int rr = row & 15, mt = row >> 4;
            int reg = (rr >> 3) + 2 * chigh;
            int idx = ((reg * 2 + kt) * 16 + mt) * 32 + (rr & 7) * 4;
            *(uint4*)&sAhi[idx] = make_uint4(h0, h1, h2, h3);
            *(uint4*)&sAlo[idx] = make_uint4(l0, l1, l2, l3);
        }
        __syncthreads();   // smem ready
        // ---- prefetch chunk c+1 (loads in flight during MMA below) ----
        if (c + 1 < 32) {
#pragma unroll
            for (int j = 0; j < 4; j++) {
                int row = arow + j * 64;
                int gr = m0 + row;
                v[j] = (gr < M) ? *(const float4*)(X + (size_t)gr * 512 + (c + 1) * 16 + acol4 * 4)
                                : make_float4(0.f, 0.f, 0.f, 0.f);
            }
        }
        // ---- MMA over 2 k8-tiles ----
#pragma unroll
        for (int kt = 0; kt < 2; kt++) {
            uint32_t ahi[2][4], alo[2][4];
#pragma unroll
            for (int m = 0; m < 2; m++) {
                int mt = w * 2 + m;
#pragma unroll
                for (int r = 0; r < 4; r++) {
                    int idx = ((r * 2 + kt) * 16 + mt) * 32 + lane;
                    ahi[m][r] = sAhi[idx];
                    alo[m][r] = sAlo[idx];
                }
            }
            int gkt = c * 2 + kt;
#pragma unroll
            for (int nt = 0; nt < 8; nt++) {
                size_t boff = ((size_t)(gkt * 8 + nt) * 32 + lane) * 2;
                uint2 bhi = *(const uint2*)(g_w1hi + boff);
                uint2 blo = *(const uint2*)(g_w1lo + boff);
#pragma unroll
                for (int m = 0; m < 2; m++) {
                    MMA_TF32(C[m][nt], ahi[m], bhi);
                    MMA_TF32(C[m][nt], ahi[m], blo);
                    MMA_TF32(C[m][nt], alo[m], bhi);
                }
            }
        }
    }

    // ---- epilogue: store xl1 (fp16) + fused attn coefficient dots ----
#pragma unroll
    for (int m = 0; m < 2; m++) {
        int mt = w * 2 + m;
#pragma unroll
        for (int half = 0; half < 2; half++) {
            int row = m0 + mt * 16 + g + half * 8;
            bool ok = row < M;
            if (ok) {
#pragma unroll
                for (int nt = 0; nt < 8; nt++) {
                    __half2 hv = __floats2half2_rn(C[m][nt][half * 2], C[m][nt][half * 2 + 1]);
                    *(__half2*)(g_xl1h + (size_t)row * 64 + nt * 8 + t * 2) = hv;
                }
            }
#pragma unroll
            for (int nt = 0; nt < 8; nt++) {
                float e0 = C[m][nt][half * 2], e1 = C[m][nt][half * 2 + 1];
                float ps = e0 * s_as[nt * 8 + t * 2] + e1 * s_as[nt * 8 + t * 2 + 1];
                float pd = e0 * s_ad[nt * 8 + t * 2] + e1 * s_ad[nt * 8 + t * 2 + 1];
                ps += __shfl_xor_sync(0xFFFFFFFFu, ps, 1);
                ps += __shfl_xor_sync(0xFFFFFFFFu, ps, 2);
                pd += __shfl_xor_sync(0xFFFFFFFFu, pd, 1);
                pd += __shfl_xor_sync(0xFFFFFFFFu, pd, 2);
                if (ok && t == 0) {
                    g_asrc1[(size_t)row * 8 + nt] = ps;
                    g_adst1[(size_t)row * 8 + nt] = pd;
                }
            }
        }
    }
}

// ===== layer1 aggregation + bias/ELU + GEMM2 + attn2 coeffs, all fused (warp/node) =====
__global__ void __launch_bounds__(256) agg1_fused_kernel(
        const float* __restrict__ bias1, const float* __restrict__ W2,
        const float* __restrict__ att_src2, const float* __restrict__ att_dst2, int n) {
    const unsigned FULL = 0xFFFFFFFFu;
    int gw = (blockIdx.x * blockDim.x + threadIdx.x) >> 5;
    int lane = threadIdx.x & 31;
    int w = threadIdx.x >> 5;
    __shared__ float sex[8][32][9];
    __shared__ int   ssrc[8][32];
    __shared__ float sh_h[8][64];
    __shared__ __align__(16) float sW2[64 * 16];
    __shared__ float sb1[64], sas2[16], sad2[16];
    {
        int tid = threadIdx.x;
        for (int i = tid; i < 1024; i += 256) sW2[i] = W2[i];
        if (tid < 64) sb1[tid] = bias1[tid];
        if (tid < 16) { sas2[tid] = att_src2[tid]; sad2[tid] = att_dst2[tid]; }
    }
    __syncthreads();
    if (gw >= n) return;
    int d = gw;
    int cnt = g_cnt[d]; if (cnt > SLOT) cnt = SLOT;
    const int* eb = g_csrc + (size_t)d * SLOT;

    float ad[8];
    {
        float4 t0 = *(const float4*)(g_adst1 + (size_t)d * 8);
        float4 t1 = *(const float4*)(g_adst1 + (size_t)d * 8 + 4);
        ad[0] = t0.x; ad[1] = t0.y; ad[2] = t0.z; ad[3] = t0.w;
        ad[4] = t1.x; ad[5] = t1.y; ad[6] = t1.z; ad[7] = t1.w;
    }

    int c2 = lane * 2;
    int hl = lane >> 2;
    float accx = 0.f, accy = 0.f;
    float dn[8];
#pragma unroll
    for (int h = 0; h < 8; h++) dn[h] = 0.f;

    for (int base = 0; base < cnt; base += 32) {
        int m = cnt - base; if (m > 32) m = 32;
        if (lane < m) {
            int s = eb[base + lane];
            ssrc[w][lane] = s;
            float4 a0 = *(const float4*)(g_asrc1 + (size_t)s * 8);
            float4 a1 = *(const float4*)(g_asrc1 + (size_t)s * 8 + 4);
            float as[8] = {a0.x, a0.y, a0.z, a0.w, a1.x, a1.y, a1.z, a1.w};
#pragma unroll
            for (int h = 0; h < 8; h++) {
                float ex = __expf(lrelu(as[h] + ad[h]));
                dn[h] += ex;
                sex[w][lane][h] = ex;
            }
        }
        __syncwarp();
        int j = 0;
        for (; j + 4 <= m; j += 4) {
            int s0 = ssrc[w][j + 0], s1 = ssrc[w][j + 1];
            int s2 = ssrc[w][j + 2], s3 = ssrc[w][j + 3];
            __half2 q0 = *(const __half2*)(g_xl1h + (size_t)s0 * 64 + c2);
            __half2 q1 = *(const __half2*)(g_xl1h + (size_t)s1 * 64 + c2);
            __half2 q2 = *(const __half2*)(g_xl1h + (size_t)s2 * 64 + c2);
            __half2 q3 = *(const __half2*)(g_xl1h + (size_t)s3 * 64 + c2);
            float e0 = sex[w][j + 0][hl], e1 = sex[w][j + 1][hl];
            float e2 = sex[w][j + 2][hl], e3 = sex[w][j + 3][hl];
            float2 v0 = __half22float2(q0), v1 = __half22float2(q1);
            float2 v2 = __half22float2(q2), v3 = __half22float2(q3);
            accx = fmaf(e0, v0.x, accx); accy = fmaf(e0, v0.y, accy);
            accx = fmaf(e1, v1.x, accx); accy = fmaf(e1, v1.y, accy);
            accx = fmaf(e2, v2.x, accx); accy = fmaf(e2, v2.y, accy);
            accx = fmaf(e3, v3.x, accx); accy = fmaf(e3, v3.y, accy);
        }
        for (; j < m; j++) {
            int sj = ssrc[w][j];
            __half2 q = *(const __half2*)(g_xl1h + (size_t)sj * 64 + c2);
            float2 v = __half22float2(q);
            float e = sex[w][j][hl];
            accx = fmaf(e, v.x, accx); accy = fmaf(e, v.y, accy);
        }
        __syncwarp();
    }
#pragma unroll
    for (int h = 0; h < 8; h++)
#pragma unroll
        for (int o = 16; o > 0; o >>= 1) dn[h] += __shfl_xor_sync(FULL, dn[h], o);

    // bias1 + ELU, stage h into smem
    {
        float inv = 1.0f / (dn[hl] + EPSV);
        float h0 = accx * inv + sb1[c2];
        float h1 = accy * inv + sb1[c2 + 1];
        h0 = h0 > 0.f ? h0 : (__expf(h0) - 1.f);
        h1 = h1 > 0.f ? h1 : (__expf(h1) - 1.f);
        sh_h[w][c2] = h0;
        sh_h[w][c2 + 1] = h1;
    }
    __syncwarp();

    // GEMM2: y[c] = sum_k h[k] * W2[k][c]; c = lane&15, k-half split across half-warps
    int cc = lane & 15, kh = lane >> 4;
    float y = 0.f;
    const float* hrow = sh_h[w];
#pragma unroll 8
    for (int k = kh * 32; k < kh * 32 + 32; k++)
        y = fmaf(hrow[k], sW2[k * 16 + cc], y);
    y += __shfl_xor_sync(FULL, y, 16);

    // attn2 dots: ss = sum_c y[c]*as2[c]
    float ps = y * sas2[cc], pd = y * sad2[cc];
#pragma unroll
    for (int o = 8; o > 0; o >>= 1) {
        ps += __shfl_xor_sync(FULL, ps, o);
        pd += __shfl_xor_sync(FULL, pd, o);
    }
    if (lane < 16) g_x2h[(size_t)d * 16 + cc] = __float2half_rn(y);
    if (lane == 0) { g_asrc2[d] = ps; g_adst2[d] = pd; }
}

// ================= layer2 aggregation: warp/node, quarter-warp/edge, half2 =================
__global__ void agg2_kernel(const float* __restrict__ bias2, float* __restrict__ out, int n) {
    const unsigned FULL = 0xFFFFFFFFu;
    int warp = (blockIdx.x * blockDim.x + threadIdx.x) >> 5;
    int lane = threadIdx.x & 31;
    int w = threadIdx.x >> 5;
    __shared__ float sex[8][33];
    __shared__ int   ssrc[8][33];
    if (warp >= n) return;
    int d = warp;
    int cnt = g_cnt[d]; if (cnt > SLOT) cnt = SLOT;
    const int* eb = g_csrc + (size_t)d * SLOT;
    float adv = g_adst2[d];

    int grp = lane >> 3;
    int lc = lane & 7;
    float accx = 0.f, accy = 0.f, dnl = 0.f;
    for (int base = 0; base < cnt; base += 32) {
        int m = cnt - base; if (m > 32) m = 32;
        if (lane < m) {
            int s = eb[base + lane];
            float ex = __expf(lrelu(g_asrc2[s] + adv));
            dnl += ex;
            ssrc[w][lane] = s;
            sex[w][lane] = ex;
        }
        __syncwarp();
        int j = grp;
        for (; j + 12 < m; j += 16) {
            int s0 = ssrc[w][j + 0], s1 = ssrc[w][j + 4];
            int s2 = ssrc[w][j + 8], s3 = ssrc[w][j + 12];
            float e0 = sex[w][j + 0], e1 = sex[w][j + 4];
            float e2 = sex[w][j + 8], e3 = sex[w][j + 12];
            __half2 q0 = *(const __half2*)(g_x2h + (size_t)s0 * 16 + lc * 2);
            __half2 q1 = *(const __half2*)(g_x2h + (size_t)s1 * 16 + lc * 2);
            __half2 q2 = *(const __half2*)(g_x2h + (size_t)s2 * 16 + lc * 2);
            __half2 q3 = *(const __half2*)(g_x2h + (size_t)s3 * 16 + lc * 2);
            float2 v0 = __half22float2(q0), v1 = __half22float2(q1);
            float2 v2 = __half22float2(q2), v3 = __half22float2(q3);
            accx = fmaf(e0, v0.x, accx); accy = fmaf(e0, v0.y, accy);
            accx = fmaf(e1, v1.x, accx); accy = fmaf(e1, v1.y, accy);
            accx = fmaf(e2, v2.x, accx); accy = fmaf(e2, v2.y, accy);
            accx = fmaf(e3, v3.x, accx); accy = fmaf(e3, v3.y, accy);
        }
        for (; j < m; j += 4) {
            int sj = ssrc[w][j];
            float ej = sex[w][j];
            __half2 q = *(const __half2*)(g_x2h + (size_t)sj * 16 + lc * 2);
            float2 v = __half22float2(q);
            accx = fmaf(ej, v.x, accx); accy = fmaf(ej, v.y, accy);
        }
        __syncwarp();
    }
#pragma unroll
    for (int o = 16; o > 0; o >>= 1) dnl += __shfl_xor_sync(FULL, dnl, o);
    accx += __shfl_xor_sync(FULL, accx, 8);
    accx += __shfl_xor_sync(FULL, accx, 16);
    accy += __shfl_xor_sync(FULL, accy, 8);
    accy += __shfl_xor_sync(FULL, accy, 16);
    if (lane < 8) {
        float inv = 1.0f / (dnl + EPSV);
        float2 o2 = make_float2(accx * inv + bias2[lc * 2], accy * inv + bias2[lc * 2 + 1]);
        *(float2*)(out + (size_t)d * 16 + lc * 2) = o2;
    }
}

// ---------------- launch ----------------
extern "C" void kernel_launch(void* const* d_in, const int* in_sizes, int n_in,
                              void* d_out, int out_size) {
    const float* x        = (const float*)d_in[0];
    const int*   ei       = (const int*)d_in[1];
    const float* W1       = (const float*)d_in[2];
    const float* att_src1 = (const float*)d_in[3];
    const float* att_dst1 = (const float*)d_in[4];
    const float* bias1    = (const float*)d_in[5];
    const float* W2       = (const float*)d_in[6];
    const float* att_src2 = (const float*)d_in[7];
    const float* att_dst2 = (const float*)d_in[8];
    const float* bias2    = (const float*)d_in[9];
    float* out = (float*)d_out;

    int n = in_sizes[0] / 512;
    int e = in_sizes[1] / 2;
    const int* src = ei;
    const int* dst = ei + e;

    int t = 256;
    zero_prep_kernel<<<(n + t - 1) / t, t>>>(W1, n);
    int gemmBlocks = (n + 255) / 256;
    int scatterBlocks = 1024;
    gemm1_mma_scatter_kernel<<<gemmBlocks + scatterBlocks, 256>>>(
        x, att_src1, att_dst1, src, dst, n, e, gemmBlocks, scatterBlocks);
    agg1_fused_kernel<<<(n * 32 + t - 1) / t, t>>>(bias1, W2, att_src2, att_dst2, n);
    agg2_kernel<<<(n * 32 + t - 1) / t, t>>>(bias2, out, n);
}

// round 16
// speedup vs baseline: 1.6513x; 1.6513x over previous
#include <cuda_runtime.h>
#include <cuda_fp16.h>
#include <cstdint>

#define NMAX 100000
#define EMAX 1600000
#define SLOT 128
#define EPSV 1e-16f

// ---------------- scratch (static device globals; no allocation) ----------------
__device__ __half g_xl1h[NMAX * 64];   // layer1 features, fp16 (gather table)
__device__ float  g_asrc1[NMAX * 8];
__device__ float  g_adst1[NMAX * 8];
__device__ __half g_x2h[NMAX * 16];    // layer2 features, fp16 (gather table)
__device__ float  g_asrc2[NMAX];
__device__ float  g_adst2[NMAX];
__device__ int g_cnt[NMAX];
__device__ int g_csrc[NMAX * SLOT];
// W1 in mma fragment layout: [ktile(64)][ntile(8)][lane(32)][reg(2)], hi & lo tf32
__device__ uint32_t g_w1hi[512 * 64];
__device__ uint32_t g_w1lo[512 * 64];

__device__ __forceinline__ float lrelu(float x) { return x > 0.0f ? x : 0.2f * x; }

__device__ __forceinline__ uint32_t f2tf32(float f) {
    uint32_t r;
    asm("cvt.rna.tf32.f32 %0, %1;" : "=r"(r) : "f"(f));
    return r;
}

#define MMA_TF32(c, a, b) \
    asm volatile("mma.sync.aligned.m16n8k8.row.col.f32.tf32.tf32.f32 " \
                 "{%0,%1,%2,%3}, {%4,%5,%6,%7}, {%8,%9}, {%0,%1,%2,%3};" \
                 : "+f"((c)[0]), "+f"((c)[1]), "+f"((c)[2]), "+f"((c)[3]) \
                 : "r"((a)[0]), "r"((a)[1]), "r"((a)[2]), "r"((a)[3]), \
                   "r"((b).x), "r"((b).y))

// ================= zero counters + W1 hi/lo fragment precompute =================
__global__ void zero_prep_kernel(const float* __restrict__ W, int n) {
    int i = blockIdx.x * blockDim.x + threadIdx.x;
    if (i < n) g_cnt[i] = 0;
    if (i < 512 * 64) {
        int k = i >> 6, nn = i & 63;
        float wv = W[i];
        uint32_t hi = f2tf32(wv);
        uint32_t lo = f2tf32(wv - __uint_as_float(hi));
        int pos = ((((k >> 3) * 8 + (nn >> 3)) * 32 + ((nn & 7) * 4 + (k & 3))) << 1) + ((k >> 2) & 1);
        g_w1hi[pos] = hi;
        g_w1lo[pos] = lo;
    }
}

// ================= fused mma.sync 3xTF32 GEMM1 (+attn coeffs) and edge scatter =================
// (R13-exact GEMM body: inline loads, no register prefetch — avoids C-spill)
__global__ void __launch_bounds__(256) gemm1_mma_scatter_kernel(
        const float* __restrict__ X,
        const float* __restrict__ att_src, const float* __restrict__ att_dst,
        const int* __restrict__ src, const int* __restrict__ dst,
        int M, int E, int gemmBlocks, int scatterBlocks) {
    if (blockIdx.x >= (unsigned)gemmBlocks) {
        int sb = blockIdx.x - gemmBlocks;
        int stride = scatterBlocks * 256;
        for (int i = sb * 256 + threadIdx.x; i < E; i += stride) {
            int d = dst[i];
            int pos = atomicAdd(&g_cnt[d], 1);
            if (pos < SLOT) g_csrc[(size_t)d * SLOT + pos] = src[i];
        }
        return;
    }
    __shared__ __align__(16) uint32_t sAhi[4096];
    __shared__ __align__(16) uint32_t sAlo[4096];
    __shared__ float s_as[64], s_ad[64];

    int tid = threadIdx.x;
    int w = tid >> 5, lane = tid & 31;
    int g = lane >> 2, t = lane & 3;
    int m0 = blockIdx.x * 256;

    if (tid < 64) { s_as[tid] = att_src[tid]; s_ad[tid] = att_dst[tid]; }

    float C[2][8][4];
#pragma unroll
    for (int m = 0; m < 2; m++)
#pragma unroll
        for (int nt = 0; nt < 8; nt++)
#pragma unroll
            for (int r = 0; r < 4; r++) C[m][nt][r] = 0.0f;

    for (int c = 0; c < 32; c++) {
        __syncthreads();
#pragma unroll
        for (int j = 0; j < 4; j++) {
            int idx4 = tid + j * 256;
            int row = idx4 >> 2, col4 = idx4 & 3;
            int grow = m0 + row;
            float4 v = (grow < M) ? *(const float4*)(X + (size_t)grow * 512 + c * 16 + col4 * 4)
                                  : make_float4(0.f, 0.f, 0.f, 0.f);
            uint32_t h0 = f2tf32(v.x), h1 = f2tf32(v.y), h2 = f2tf32(v.z), h3 = f2tf32(v.w);
            uint32_t l0 = f2tf32(v.x - __uint_as_float(h0));
            uint32_t l1 = f2tf32(v.y - __uint_as_float(h1));
            uint32_t l2 = f2tf32(v.z - __uint_as_float(h2));
            uint32_t l3 = f2tf32(v.w - __uint_as_float(h3));
            int kt = col4 >> 1, chigh = col4 & 1;
            int rr = row & 15, mt = row >> 4;
            int reg = (rr >> 3) + 2 * chigh;
            int idx = ((reg * 2 + kt) * 16 + mt) * 32 + (rr & 7) * 4;
            *(uint4*)&sAhi[idx] = make_uint4(h0, h1, h2, h3);
            *(uint4*)&sAlo[idx] = make_uint4(l0, l1, l2, l3);
        }
        __syncthreads();
#pragma unroll
        for (int kt = 0; kt < 2; kt++) {
            uint32_t ahi[2][4], alo[2][4];
#pragma unroll
            for (int m = 0; m < 2; m++) {
                int mt = w * 2 + m;
#pragma unroll
                for (int r = 0; r < 4; r++) {
                    int idx = ((r * 2 + kt) * 16 + mt) * 32 + lane;
                    ahi[m][r] = sAhi[idx];
                    alo[m][r] = sAlo[idx];
                }
            }
            int gkt = c * 2 + kt;
#pragma unroll
            for (int nt = 0; nt < 8; nt++) {
                size_t boff = ((size_t)(gkt * 8 + nt) * 32 + lane) * 2;
                uint2 bhi = *(const uint2*)(g_w1hi + boff);
                uint2 blo = *(const uint2*)(g_w1lo + boff);
#pragma unroll
                for (int m = 0; m < 2; m++) {
                    MMA_TF32(C[m][nt], ahi[m], bhi);
                    MMA_TF32(C[m][nt], ahi[m], blo);
                    MMA_TF32(C[m][nt], alo[m], bhi);
                }
            }
        }
    }

    // ---- epilogue: store xl1 (fp16) + fused attn coefficient dots ----
#pragma unroll
    for (int m = 0; m < 2; m++) {
        int mt = w * 2 + m;
#pragma unroll
        for (int half = 0; half < 2; half++) {
            int row = m0 + mt * 16 + g + half * 8;
            bool ok = row < M;
            if (ok) {
#pragma unroll
                for (int nt = 0; nt < 8; nt++) {
                    __half2 hv = __floats2half2_rn(C[m][nt][half * 2], C[m][nt][half * 2 + 1]);
                    *(__half2*)(g_xl1h + (size_t)row * 64 + nt * 8 + t * 2) = hv;
                }
            }
#pragma unroll
            for (int nt = 0; nt < 8; nt++) {
                float e0 = C[m][nt][half * 2], e1 = C[m][nt][half * 2 + 1];
                float ps = e0 * s_as[nt * 8 + t * 2] + e1 * s_as[nt * 8 + t * 2 + 1];
                float pd = e0 * s_ad[nt * 8 + t * 2] + e1 * s_ad[nt * 8 + t * 2 + 1];
                ps += __shfl_xor_sync(0xFFFFFFFFu, ps, 1);
                ps += __shfl_xor_sync(0xFFFFFFFFu, ps, 2);
                pd += __shfl_xor_sync(0xFFFFFFFFu, pd, 1);
                pd += __shfl_xor_sync(0xFFFFFFFFu, pd, 2);
                if (ok && t == 0) {
                    g_asrc1[(size_t)row * 8 + nt] = ps;
                    g_adst1[(size_t)row * 8 + nt] = pd;
                }
            }
        }
    }
}

// ===== layer1 aggregation + bias/ELU + GEMM2 + attn2 coeffs, all fused (warp/node) =====
__global__ void __launch_bounds__(256) agg1_fused_kernel(
        const float* __restrict__ bias1, const float* __restrict__ W2,
        const float* __restrict__ att_src2, const float* __restrict__ att_dst2, int n) {
    const unsigned FULL = 0xFFFFFFFFu;
    int gw = (blockIdx.x * blockDim.x + threadIdx.x) >> 5;
    int lane = threadIdx.x & 31;
    int w = threadIdx.x >> 5;
    __shared__ float sex[8][32][9];
    __shared__ int   ssrc[8][32];
    __shared__ float sh_h[8][64];
    __shared__ __align__(16) float sW2[64 * 16];
    __shared__ float sb1[64], sas2[16], sad2[16];
    {
        int tid = threadIdx.x;
        for (int i = tid; i < 1024; i += 256) sW2[i] = W2[i];
        if (tid < 64) sb1[tid] = bias1[tid];
        if (tid < 16) { sas2[tid] = att_src2[tid]; sad2[tid] = att_dst2[tid]; }
    }
    __syncthreads();
    if (gw >= n) return;
    int d = gw;
    int cnt = g_cnt[d]; if (cnt > SLOT) cnt = SLOT;
    const int* eb = g_csrc + (size_t)d * SLOT;

    float ad[8];
    {
        float4 t0 = *(const float4*)(g_adst1 + (size_t)d * 8);
        float4 t1 = *(const float4*)(g_adst1 + (size_t)d * 8 + 4);
        ad[0] = t0.x; ad[1] = t0.y; ad[2] = t0.z; ad[3] = t0.w;
        ad[4] = t1.x; ad[5] = t1.y; ad[6] = t1.z; ad[7] = t1.w;
    }

    int c2 = lane * 2;
    int hl = lane >> 2;
    float accx = 0.f, accy = 0.f;
    float dn[8];
#pragma unroll
    for (int h = 0; h < 8; h++) dn[h] = 0.f;

    for (int base = 0; base < cnt; base += 32) {
        int m = cnt - base; if (m > 32) m = 32;
        if (lane < m) {
            int s = eb[base + lane];
            ssrc[w][lane] = s;
            float4 a0 = *(const float4*)(g_asrc1 + (size_t)s * 8);
            float4 a1 = *(const float4*)(g_asrc1 + (size_t)s * 8 + 4);
            float as[8] = {a0.x, a0.y, a0.z, a0.w, a1.x, a1.y, a1.z, a1.w};
#pragma unroll
            for (int h = 0; h < 8; h++) {
                float ex = __expf(lrelu(as[h] + ad[h]));
                dn[h] += ex;
                sex[w][lane][h] = ex;
            }
        }
        __syncwarp();
        int j = 0;
        for (; j + 4 <= m; j += 4) {
            int s0 = ssrc[w][j + 0], s1 = ssrc[w][j + 1];
            int s2 = ssrc[w][j + 2], s3 = ssrc[w][j + 3];
            __half2 q0 = *(const __half2*)(g_xl1h + (size_t)s0 * 64 + c2);
            __half2 q1 = *(const __half2*)(g_xl1h + (size_t)s1 * 64 + c2);
            __half2 q2 = *(const __half2*)(g_xl1h + (size_t)s2 * 64 + c2);
            __half2 q3 = *(const __half2*)(g_xl1h + (size_t)s3 * 64 + c2);
            float e0 = sex[w][j + 0][hl], e1 = sex[w][j + 1][hl];
            float e2 = sex[w][j + 2][hl], e3 = sex[w][j + 3][hl];
            float2 v0 = __half22float2(q0), v1 = __half22float2(q1);
            float2 v2 = __half22float2(q2), v3 = __half22float2(q3);
            accx = fmaf(e0, v0.x, accx); accy = fmaf(e0, v0.y, accy);
            accx = fmaf(e1, v1.x, accx); accy = fmaf(e1, v1.y, accy);
            accx = fmaf(e2, v2.x, accx); accy = fmaf(e2, v2.y, accy);
            accx = fmaf(e3, v3.x, accx); accy = fmaf(e3, v3.y, accy);
        }
        for (; j < m; j++) {
            int sj = ssrc[w][j];
            __half2 q = *(const __half2*)(g_xl1h + (size_t)sj * 64 + c2);
            float2 v = __half22float2(q);
            float e = sex[w][j][hl];
            accx = fmaf(e, v.x, accx); accy = fmaf(e, v.y, accy);
        }
        __syncwarp();
    }
#pragma unroll
    for (int h = 0; h < 8; h++)
#pragma unroll
        for (int o = 16; o > 0; o >>= 1) dn[h] += __shfl_xor_sync(FULL, dn[h], o);

    // bias1 + ELU, stage h into smem
    {
        float inv = 1.0f / (dn[hl] + EPSV);
        float h0 = accx * inv + sb1[c2];
        float h1 = accy * inv + sb1[c2 + 1];
        h0 = h0 > 0.f ? h0 : (__expf(h0) - 1.f);
        h1 = h1 > 0.f ? h1 : (__expf(h1) - 1.f);
        sh_h[w][c2] = h0;
        sh_h[w][c2 + 1] = h1;
    }
    __syncwarp();

    // GEMM2: y[c] = sum_k h[k] * W2[k][c]; c = lane&15, k-half split across half-warps
    int cc = lane & 15, kh = lane >> 4;
    float y = 0.f;
    const float* hrow = sh_h[w];
#pragma unroll 8
    for (int k = kh * 32; k < kh * 32 + 32; k++)
        y = fmaf(hrow[k], sW2[k * 16 + cc], y);
    y += __shfl_xor_sync(FULL, y, 16);

    // attn2 dots
    float ps = y * sas2[cc], pd = y * sad2[cc];
#pragma unroll
    for (int o = 8; o > 0; o >>= 1) {
        ps += __shfl_xor_sync(FULL, ps, o);
        pd += __shfl_xor_sync(FULL, pd, o);
    }
    if (lane < 16) g_x2h[(size_t)d * 16 + cc] = __float2half_rn(y);
    if (lane == 0) { g_asrc2[d] = ps; g_adst2[d] = pd; }
}

// ================= layer2 aggregation: warp/node, quarter-warp/edge, half2 =================
__global__ void agg2_kernel(const float* __restrict__ bias2, float* __restrict__ out, int n) {
    const unsigned FULL = 0xFFFFFFFFu;
    int warp = (blockIdx.x * blockDim.x + threadIdx.x) >> 5;
    int lane = threadIdx.x & 31;
    int w = threadIdx.x >> 5;
    __shared__ float sex[8][33];
    __shared__ int   ssrc[8][33];
    if (warp >= n) return;
    int d = warp;
    int cnt = g_cnt[d]; if (cnt > SLOT) cnt = SLOT;
    const int* eb = g_csrc + (size_t)d * SLOT;
    float adv = g_adst2[d];

    int grp = lane >> 3;
    int lc = lane & 7;
    float accx = 0.f, accy = 0.f, dnl = 0.f;
    for (int base = 0; base < cnt; base += 32) {
        int m = cnt - base; if (m > 32) m = 32;
        if (lane < m) {
            int s = eb[base + lane];
            float ex = __expf(lrelu(g_asrc2[s] + adv));
            dnl += ex;
            ssrc[w][lane] = s;
            sex[w][lane] = ex;
        }
        __syncwarp();
        int j = grp;
        for (; j + 12 < m; j += 16) {
            int s0 = ssrc[w][j + 0], s1 = ssrc[w][j + 4];
            int s2 = ssrc[w][j + 8], s3 = ssrc[w][j + 12];
            float e0 = sex[w][j + 0], e1 = sex[w][j + 4];
            float e2 = sex[w][j + 8], e3 = sex[w][j + 12];
            __half2 q0 = *(const __half2*)(g_x2h + (size_t)s0 * 16 + lc * 2);
            __half2 q1 = *(const __half2*)(g_x2h + (size_t)s1 * 16 + lc * 2);
            __half2 q2 = *(const __half2*)(g_x2h + (size_t)s2 * 16 + lc * 2);
            __half2 q3 = *(const __half2*)(g_x2h + (size_t)s3 * 16 + lc * 2);
            float2 v0 = __half22float2(q0), v1 = __half22float2(q1);
            float2 v2 = __half22float2(q2), v3 = __half22float2(q3);
            accx = fmaf(e0, v0.x, accx); accy = fmaf(e0, v0.y, accy);
            accx = fmaf(e1, v1.x, accx); accy = fmaf(e1, v1.y, accy);
            accx = fmaf(e2, v2.x, accx); accy = fmaf(e2, v2.y, accy);
            accx = fmaf(e3, v3.x, accx); accy = fmaf(e3, v3.y, accy);
        }
        for (; j < m; j += 4) {
            int sj = ssrc[w][j];
            float ej = sex[w][j];
            __half2 q = *(const __half2*)(g_x2h + (size_t)sj * 16 + lc * 2);
            float2 v = __half22float2(q);
            accx = fmaf(ej, v.x, accx); accy = fmaf(ej, v.y, accy);
        }
        __syncwarp();
    }
#pragma unroll
    for (int o = 16; o > 0; o >>= 1) dnl += __shfl_xor_sync(FULL, dnl, o);
    accx += __shfl_xor_sync(FULL, accx, 8);
    accx += __shfl_xor_sync(FULL, accx, 16);
    accy += __shfl_xor_sync(FULL, accy, 8);
    accy += __shfl_xor_sync(FULL, accy, 16);
    if (lane < 8) {
        float inv = 1.0f / (dnl + EPSV);
        float2 o2 = make_float2(accx * inv + bias2[lc * 2], accy * inv + bias2[lc * 2 + 1]);
        *(float2*)(out + (size_t)d * 16 + lc * 2) = o2;
    }
}

// ---------------- launch ----------------
extern "C" void kernel_launch(void* const* d_in, const int* in_sizes, int n_in,
                              void* d_out, int out_size) {
    const float* x        = (const float*)d_in[0];
    const int*   ei       = (const int*)d_in[1];
    const float* W1       = (const float*)d_in[2];
    const float* att_src1 = (const float*)d_in[3];
    const float* att_dst1 = (const float*)d_in[4];
    const float* bias1    = (const float*)d_in[5];
    const float* W2       = (const float*)d_in[6];
    const float* att_src2 = (const float*)d_in[7];
    const float* att_dst2 = (const float*)d_in[8];
    const float* bias2    = (const float*)d_in[9];
    float* out = (float*)d_out;

    int n = in_sizes[0] / 512;
    int e = in_sizes[1] / 2;
    const int* src = ei;
    const int* dst = ei + e;

    int t = 256;
    zero_prep_kernel<<<(n + t - 1) / t, t>>>(W1, n);
    int gemmBlocks = (n + 255) / 256;
    int scatterBlocks = 1024;
    gemm1_mma_scatter_kernel<<<gemmBlocks + scatterBlocks, 256>>>(
        x, att_src1, att_dst1, src, dst, n, e, gemmBlocks, scatterBlocks);
    agg1_fused_kernel<<<(n * 32 + t - 1) / t, t>>>(bias1, W2, att_src2, att_dst2, n);
    agg2_kernel<<<(n * 32 + t - 1) / t, t>>>(bias2, out, n);
}